// round 16
// baseline (speedup 1.0000x reference)
#include <cuda_runtime.h>
#include <cuda_fp16.h>
#include <cstdint>
#include <math.h>

#define BB 2
#define LL 2048
#define DD 1024
#define HH 16
#define HD 64
#define FF 4096
#define MROWS (BB*LL)   // 4096

// ---------------- scratch (device globals) ---------------------------------
__device__ __half g_xn  [MROWS * DD];
__device__ __half g_qk  [MROWS * 4 * DD];   // silu(xn@w_qkuv) fp16
__device__ __half g_a   [MROWS * DD];
__device__ float  g_x1  [MROWS * DD];
__device__ __half g_xn2 [MROWS * DD];
__device__ __half g_h   [MROWS * FF];
// weights in NATIVE [K, N] layout, fp16 (no transpose)
__device__ __half g_wqkuv [DD * 4 * DD];
__device__ __half g_wout  [DD * DD];
__device__ __half g_w1    [DD * FF];
__device__ __half g_w3    [DD * FF];
__device__ __half g_w2    [FF * DD];

__device__ __forceinline__ float silu(float x) {
    return __fdividef(x, 1.0f + __expf(-x));
}
__device__ __forceinline__ uint32_t smem_u32(const void* p) {
    uint32_t a;
    asm("{ .reg .u64 t; cvta.to.shared.u64 t, %1; cvt.u32.u64 %0, t; }" : "=r"(a) : "l"(p));
    return a;
}
__device__ __forceinline__ void cp16(uint32_t s, const void* g) {
    asm volatile("cp.async.cg.shared.global [%0], [%1], 16;" :: "r"(s), "l"(g) : "memory");
}
#define CPCOMMIT() asm volatile("cp.async.commit_group;" ::: "memory")
#define CPWAIT(n)  asm volatile("cp.async.wait_group %0;" :: "n"(n) : "memory")
__device__ __forceinline__ uint32_t pack2h(__half a, __half b) {
    return (uint32_t)__half_as_ushort(a) | ((uint32_t)__half_as_ushort(b) << 16);
}
__device__ __forceinline__ void ldsm4(uint32_t* r, uint32_t a) {
    asm volatile("ldmatrix.sync.aligned.m8n8.x4.shared.b16 {%0,%1,%2,%3}, [%4];"
        : "=r"(r[0]), "=r"(r[1]), "=r"(r[2]), "=r"(r[3]) : "r"(a));
}
__device__ __forceinline__ void ldsm4t(uint32_t* r, uint32_t a) {
    asm volatile("ldmatrix.sync.aligned.m8n8.x4.trans.shared.b16 {%0,%1,%2,%3}, [%4];"
        : "=r"(r[0]), "=r"(r[1]), "=r"(r[2]), "=r"(r[3]) : "r"(a));
}
__device__ __forceinline__ void mma16816(float* c, const uint32_t* a, uint32_t b0, uint32_t b1) {
    asm volatile(
        "mma.sync.aligned.m16n8k16.row.col.f32.f16.f16.f32 "
        "{%0,%1,%2,%3}, {%4,%5,%6,%7}, {%8,%9}, {%0,%1,%2,%3};"
        : "+f"(c[0]), "+f"(c[1]), "+f"(c[2]), "+f"(c[3])
        : "r"(a[0]), "r"(a[1]), "r"(a[2]), "r"(a[3]), "r"(b0), "r"(b1));
}

// ---------------- fp32 -> fp16 chunk convert (32768 elems per CTA) ----------
__device__ __forceinline__ void conv_chunk(const float* __restrict__ src,
                                           __half* __restrict__ dst,
                                           int cta, int tid)
{
    size_t base = (size_t)cta * 32768;
    #pragma unroll
    for (int it = 0; it < 32; it++) {
        size_t idx = base + (size_t)(it * 256 + tid) * 4;
        float4 v = *(const float4*)(src + idx);
        *(uint2*)(dst + idx) = make_uint2(
            pack2h(__float2half(v.x), __float2half(v.y)),
            pack2h(__float2half(v.z), __float2half(v.w)));
    }
}

// ---------------- LayerNorm row (warp-per-row body) --------------------------
__device__ __forceinline__ void ln_row(const float* __restrict__ xr,
                                       const float* __restrict__ g,
                                       const float* __restrict__ b,
                                       __half* __restrict__ orow, int lid)
{
    float s = 0.f, s2 = 0.f;
    float4 q4[8];
    #pragma unroll
    for (int j = 0; j < 8; j++) {
        q4[j] = *(const float4*)(xr + j * 128 + lid * 4);
        s  += q4[j].x + q4[j].y + q4[j].z + q4[j].w;
        s2 += q4[j].x * q4[j].x + q4[j].y * q4[j].y
            + q4[j].z * q4[j].z + q4[j].w * q4[j].w;
    }
    #pragma unroll
    for (int off = 16; off > 0; off >>= 1) {
        s  += __shfl_xor_sync(0xffffffffu, s,  off);
        s2 += __shfl_xor_sync(0xffffffffu, s2, off);
    }
    float mu = s * (1.0f / DD);
    float var = s2 * (1.0f / DD) - mu * mu;
    float rstd = rsqrtf(var + 1e-5f);
    #pragma unroll
    for (int j = 0; j < 8; j++) {
        int c = j * 128 + lid * 4;
        float4 gg = *(const float4*)(g + c);
        float4 bb = *(const float4*)(b + c);
        __half h0 = __float2half((q4[j].x - mu) * rstd * gg.x + bb.x);
        __half h1 = __float2half((q4[j].y - mu) * rstd * gg.y + bb.y);
        __half h2 = __float2half((q4[j].z - mu) * rstd * gg.z + bb.z);
        __half h3 = __float2half((q4[j].w - mu) * rstd * gg.w + bb.w);
        *(uint2*)(orow + c) = make_uint2(pack2h(h0, h1), pack2h(h2, h3));
    }
}

// ---------------- LN1 + wqkuv convert, fused launch --------------------------
__global__ __launch_bounds__(256) void ln_conv_kernel(
    const float* __restrict__ x, const float* __restrict__ g,
    const float* __restrict__ b, __half* __restrict__ o,
    const float* __restrict__ wsrc, __half* __restrict__ wdst)
{
    int bid = blockIdx.x;
    int wid = threadIdx.x >> 5, lid = threadIdx.x & 31;
    if (bid < MROWS / 8) {
        int row = bid * 8 + wid;
        ln_row(x + (size_t)row * DD, g, b, o + (size_t)row * DD, lid);
    } else {
        conv_chunk(wsrc, wdst, bid - MROWS / 8, threadIdx.x);
    }
}

// ---------------- LayerNorm standalone (LN2) ---------------------------------
__global__ __launch_bounds__(256) void ln_half_kernel(
    const float* __restrict__ x, const float* __restrict__ g,
    const float* __restrict__ b, __half* __restrict__ o)
{
    int wid = threadIdx.x >> 5, lid = threadIdx.x & 31;
    int row = blockIdx.x * 8 + wid;
    ln_row(x + (size_t)row * DD, g, b, o + (size_t)row * DD, lid);
}

// ---------------- fp16 GEMM: D[M,N] = A[M,K] @ W[K,N] ------------------------
// MODE 1: Cf = acc + aux (fp32 out).  MODE 3: silu(acc) -> Ch fp16.
// CTA 128x128, BK=64, warp 64x32 (2x4), 3-stage, 2 CTAs/SM.
#define SROW 144
#define WROWB 272
#define AT (128 * SROW)             // 18432
#define WT (64 * WROWB)             // 17408
#define STAGE3 (AT + WT)            // 35840
#define GEMM_SMEM (3 * STAGE3)      // 107520

template <int MODE>
__global__ __launch_bounds__(256, 2) void gemm_mma(
    const __half* __restrict__ A, const __half* __restrict__ Bw,
    float* __restrict__ Cf, const float* __restrict__ aux,
    __half* __restrict__ Ch,
    int M, int N, int K)
{
    extern __shared__ char smem[];
    const uint32_t sbase = smem_u32(smem);
    const int tid = threadIdx.x, lane = tid & 31, wid = tid >> 5;
    const int wm = wid & 1, wn = wid >> 1;
    const int bx = blockIdx.x, by = blockIdx.y;

    const size_t rowbytesA = (size_t)K * 2;
    const size_t rowbytesB = (size_t)N * 2;
    const char* Ab = (const char*)(A + (size_t)by * 128 * K);
    const char* Bb = (const char*)Bw + (size_t)bx * 256;

    const uint32_t aRowOff = (uint32_t)((wm * 64 + (lane & 15)) * SROW + (lane >> 4) * 16);
    const int bg = lane >> 3;
    const uint32_t bOffW = (uint32_t)(((bg & 1) * 8 + (lane & 7)) * WROWB
                                      + (wn * 32 + (bg >> 1) * 8) * 2);

    auto load_slab = [&](int ks, int st) {
        uint32_t stg = sbase + (uint32_t)st * STAGE3;
        size_t akoff = (size_t)ks * 128;
        size_t bk0 = (size_t)ks * 64;
        #pragma unroll
        for (int i = 0; i < 8; i++) {
            int c = tid + i * 256;
            if (c < 1024) {
                int rr = c >> 3, ck = (c & 7) * 16;
                cp16(stg + (uint32_t)(rr * SROW + ck),
                     Ab + (size_t)rr * rowbytesA + akoff + ck);
            } else {
                int j = c - 1024;
                int rr = j >> 4, ck = (j & 15) * 16;
                cp16(stg + (uint32_t)(AT + rr * WROWB + ck),
                     Bb + (bk0 + rr) * rowbytesB + ck);
            }
        }
        CPCOMMIT();
    };

    float acc[4][4][4];
    #pragma unroll
    for (int mt = 0; mt < 4; mt++)
        #pragma unroll
        for (int nt = 0; nt < 4; nt++)
            #pragma unroll
            for (int j = 0; j < 4; j++) acc[mt][nt][j] = 0.f;

    const int ns = K >> 6;
    load_slab(0, 0);
    if (ns > 1) load_slab(1, 1);

    for (int i = 0; i < ns; i++) {
        if (i + 1 < ns) CPWAIT(1);
        else            CPWAIT(0);
        __syncthreads();
        if (i + 2 < ns) load_slab(i + 2, (i + 2) % 3);

        uint32_t stg = sbase + (uint32_t)(i % 3) * STAGE3;
        uint32_t aB = stg + aRowOff;
        uint32_t bB = stg + AT + bOffW;

        #pragma unroll
        for (int ks = 0; ks < 4; ks++) {
            uint32_t ah[4][4], bh[2][4];
            #pragma unroll
            for (int mt = 0; mt < 4; mt++)
                ldsm4(ah[mt], aB + (uint32_t)(mt * 16 * SROW + ks * 32));
            #pragma unroll
            for (int p = 0; p < 2; p++)
                ldsm4t(bh[p], bB + (uint32_t)(ks * 16 * WROWB + p * 32));
            #pragma unroll
            for (int mt = 0; mt < 4; mt++)
                #pragma unroll
                for (int nt = 0; nt < 4; nt++) {
                    int p = nt >> 1, o = (nt & 1) * 2;
                    mma16816(acc[mt][nt], ah[mt], bh[p][o], bh[p][o + 1]);
                }
        }
    }

    const int groupID = lane >> 2, tid4 = lane & 3;
    #pragma unroll
    for (int mt = 0; mt < 4; mt++) {
        int r0 = by * 128 + wm * 64 + mt * 16 + groupID;
        #pragma unroll
        for (int nt = 0; nt < 4; nt++) {
            int cg = bx * 128 + wn * 32 + nt * 8 + tid4 * 2;
            float* a = acc[mt][nt];
            #pragma unroll
            for (int half = 0; half < 2; half++) {
                size_t off = (size_t)(r0 + half * 8) * N + cg;
                float v0 = a[half * 2 + 0], v1 = a[half * 2 + 1];
                if (MODE == 1) {
                    float2 ax = *(const float2*)(aux + off);
                    float2 o; o.x = v0 + ax.x; o.y = v1 + ax.y;
                    *(float2*)(Cf + off) = o;
                } else {
                    *(uint32_t*)(Ch + off) = pack2h(__float2half(silu(v0)),
                                                    __float2half(silu(v1)));
                }
            }
        }
    }
}

// ---------------- dual GEMM: h = silu(A@W1) * (A@W3) -> fp16 (3-stage) -------
#define DWROWB 144
#define DWT (64 * DWROWB)                 // 9216
#define DSTAGE (AT + 2 * DWT)             // 36864
#define DUAL_SMEM (3 * DSTAGE)            // 110592

__global__ __launch_bounds__(256, 2) void gemm_dual(
    const __half* __restrict__ A,
    const __half* __restrict__ B1, const __half* __restrict__ B3,
    __half* __restrict__ Ch,
    int M, int N, int K)
{
    extern __shared__ char smem[];
    const uint32_t sbase = smem_u32(smem);
    const int tid = threadIdx.x, lane = tid & 31, wid = tid >> 5;
    const int wm = wid & 1, wn = wid >> 1;
    const int bx = blockIdx.x, by = blockIdx.y;

    const size_t rowbytesA = (size_t)K * 2;
    const size_t rowbytesB = (size_t)N * 2;
    const char* Ab  = (const char*)(A + (size_t)by * 128 * K);
    const char* B1b = (const char*)B1 + (size_t)bx * 128;
    const char* B3b = (const char*)B3 + (size_t)bx * 128;

    const uint32_t aRowOff = (uint32_t)((wm * 64 + (lane & 15)) * SROW + (lane >> 4) * 16);
    const int bg = lane >> 3;
    const uint32_t bOffW = (uint32_t)(((bg & 1) * 8 + (lane & 7)) * DWROWB
                                      + (wn * 16 + (bg >> 1) * 8) * 2);

    auto load_slab = [&](int ks, int st) {
        uint32_t stg = sbase + (uint32_t)st * DSTAGE;
        size_t akoff = (size_t)ks * 128;
        size_t bk0 = (size_t)ks * 64;
        #pragma unroll
        for (int i = 0; i < 8; i++) {
            int c = tid + i * 256;
            if (c < 1024) {
                int rr = c >> 3, ck = (c & 7) * 16;
                cp16(stg + (uint32_t)(rr * SROW + ck),
                     Ab + (size_t)rr * rowbytesA + akoff + ck);
            } else {
                int j = c - 1024;
                int tw = j >> 9;
                int jj = j & 511;
                int rr = jj >> 3, ck = (jj & 7) * 16;
                cp16(stg + (uint32_t)(AT + tw * DWT + rr * DWROWB + ck),
                     (tw ? B3b : B1b) + (bk0 + rr) * rowbytesB + ck);
            }
        }
        CPCOMMIT();
    };

    float acc1[4][2][4], acc3[4][2][4];
    #pragma unroll
    for (int mt = 0; mt < 4; mt++)
        #pragma unroll
        for (int nt = 0; nt < 2; nt++)
            #pragma unroll
            for (int j = 0; j < 4; j++) { acc1[mt][nt][j] = 0.f; acc3[mt][nt][j] = 0.f; }

    const int ns = K >> 6;
    load_slab(0, 0);
    if (ns > 1) load_slab(1, 1);

    for (int i = 0; i < ns; i++) {
        if (i + 1 < ns) CPWAIT(1);
        else            CPWAIT(0);
        __syncthreads();
        if (i + 2 < ns) load_slab(i + 2, (i + 2) % 3);

        uint32_t stg = sbase + (uint32_t)(i % 3) * DSTAGE;
        uint32_t aB  = stg + aRowOff;
        uint32_t b1B = stg + AT + bOffW;
        uint32_t b3B = stg + AT + DWT + bOffW;

        #pragma unroll
        for (int ks = 0; ks < 4; ks++) {
            uint32_t ah[4][4], b1h[4], b3h[4];
            #pragma unroll
            for (int mt = 0; mt < 4; mt++)
                ldsm4(ah[mt], aB + (uint32_t)(mt * 16 * SROW + ks * 32));
            uint32_t ko = (uint32_t)(ks * 16 * DWROWB);
            ldsm4t(b1h, b1B + ko);
            ldsm4t(b3h, b3B + ko);
            #pragma unroll
            for (int mt = 0; mt < 4; mt++)
                #pragma unroll
                for (int nt = 0; nt < 2; nt++) {
                    int o = nt * 2;
                    mma16816(acc1[mt][nt], ah[mt], b1h[o], b1h[o + 1]);
                    mma16816(acc3[mt][nt], ah[mt], b3h[o], b3h[o + 1]);
                }
        }
    }

    const int groupID = lane >> 2, tid4 = lane & 3;
    #pragma unroll
    for (int mt = 0; mt < 4; mt++) {
        int r0 = by * 128 + wm * 64 + mt * 16 + groupID;
        #pragma unroll
        for (int nt = 0; nt < 2; nt++) {
            int cg = bx * 64 + wn * 16 + nt * 8 + tid4 * 2;
            #pragma unroll
            for (int half = 0; half < 2; half++) {
                size_t off = (size_t)(r0 + half * 8) * N + cg;
                float t0 = silu(acc1[mt][nt][half * 2 + 0]) * acc3[mt][nt][half * 2 + 0];
                float t1 = silu(acc1[mt][nt][half * 2 + 1]) * acc3[mt][nt][half * 2 + 1];
                *(uint32_t*)(Ch + off) = pack2h(__float2half(t0), __float2half(t1));
            }
        }
    }
}

// ---------------- Fused attention + late weight conversions ------------------
#define AROWB 144
#define SROWB 272
#define ATT_SMEM 108544
#define GROWB 8192
#define ATT_CTAS 512
#define CONV_CTAS 416

__global__ __launch_bounds__(256, 2) void attn_mma(
    const __half* __restrict__ qk,
    const float* __restrict__ nag, const float* __restrict__ nab,
    __half* __restrict__ aout,
    const float* __restrict__ woF, __half* __restrict__ woH,
    const float* __restrict__ w1F, __half* __restrict__ w1H,
    const float* __restrict__ w3F, __half* __restrict__ w3H,
    const float* __restrict__ w2F, __half* __restrict__ w2H)
{
    const int bid = blockIdx.x;
    const int tid = threadIdx.x;
    if (bid >= ATT_CTAS) {
        int j = bid - ATT_CTAS;
        if (j < 32)        conv_chunk(woF, woH, j, tid);
        else if (j < 160)  conv_chunk(w1F, w1H, j - 32, tid);
        else if (j < 288)  conv_chunk(w3F, w3H, j - 160, tid);
        else               conv_chunk(w2F, w2H, j - 288, tid);
        return;
    }

    extern __shared__ char smc[];
    const uint32_t sb = smem_u32(smc);
    const uint32_t oQ = 0;
    const uint32_t oK[2] = {18432, 36864};
    const uint32_t oV = 55296;
    const uint32_t oS = 73728;
    __half* sp = (__half*)(smc + oS);
    float* aS = (float*)(smc + oS);
    __shared__ float mu_s[128], rs_s[128];

    const int qb = 15 - (bid >> 5);
    const int bh = bid & 31;
    const int b = bh >> 4, h = bh & 15;
    const int lane = tid & 31, wid = tid >> 5;
    const int wm = wid & 1, wn = wid >> 1;
    const int groupID = lane >> 2, tid4 = lane & 3;

    const char* gq = (const char*)qk + (size_t)(b * LL) * GROWB + h * 128;

    auto ldt = [&](uint32_t so, const char* g) {
        #pragma unroll
        for (int i = 0; i < 4; i++) {
            int idx = tid + i * 256;
            int r = idx >> 3, ck = (idx & 7) * 16;
            cp16(sb + so + (uint32_t)(r * AROWB + ck), g + (size_t)r * GROWB + ck);
        }
    };

    ldt(oQ, gq + (size_t)(qb * 128) * GROWB);
    ldt(oK[0], gq + 2048);
    CPCOMMIT();

    const uint32_t aOffQ = (uint32_t)((wm * 64 + (lane & 15)) * AROWB + (lane >> 4) * 16);
    const int bg = lane >> 3;
    const uint32_t bOffK = (uint32_t)((wn * 32 + (bg >> 1) * 8 + (lane & 7)) * AROWB + (bg & 1) * 16);
    const uint32_t aOffS = (uint32_t)((wm * 64 + (lane & 15)) * SROWB + (lane >> 4) * 16);
    const uint32_t bOffV = (uint32_t)(((bg & 1) * 8 + (lane & 7)) * AROWB + (wn * 16 + (bg >> 1) * 8) * 2);

    float oacc[4][2][4];
    #pragma unroll
    for (int mt = 0; mt < 4; mt++)
        #pragma unroll
        for (int nt = 0; nt < 2; nt++)
            #pragma unroll
            for (int j = 0; j < 4; j++) oacc[mt][nt][j] = 0.f;

    for (int kb = 0; kb <= qb; kb++) {
        const int st = kb & 1;
        const bool more = (kb < qb);
        __syncthreads();
        ldt(oV, gq + 4096 + (size_t)(kb * 128) * GROWB);
        CPCOMMIT();
        if (more) {
            ldt(oK[st ^ 1], gq + 2048 + (size_t)((kb + 1) * 128) * GROWB);
            CPCOMMIT();
        }
        if (more) CPWAIT(2); else CPWAIT(1);
        __syncthreads();

        float sacc[4][4][4];
        #pragma unroll
        for (int mt = 0; mt < 4; mt++)
            #pragma unroll
            for (int nt = 0; nt < 4; nt++)
                #pragma unroll
                for (int j = 0; j < 4; j++) sacc[mt][nt][j] = 0.f;

        #pragma unroll
        for (int ks = 0; ks < 4; ks++) {
            uint32_t q4[4][4], k4[2][4];
            #pragma unroll
            for (int mt = 0; mt < 4; mt++)
                ldsm4(q4[mt], sb + oQ + aOffQ + (uint32_t)(mt * 16 * AROWB + ks * 32));
            #pragma unroll
            for (int p = 0; p < 2; p++)
                ldsm4(k4[p], sb + oK[st] + bOffK + (uint32_t)(p * 16 * AROWB + ks * 32));
            #pragma unroll
            for (int mt = 0; mt < 4; mt++)
                #pragma unroll
                for (int nt = 0; nt < 4; nt++) {
                    int p = nt >> 1, o = (nt & 1) * 2;
                    mma16816(sacc[mt][nt], q4[mt], k4[p][o], k4[p][o + 1]);
                }
        }

        const bool diag = (kb == qb);
        #pragma unroll
        for (int mt = 0; mt < 4; mt++) {
            #pragma unroll
            for (int half = 0; half < 2; half++) {
                int r = wm * 64 + mt * 16 + groupID + half * 8;
                #pragma unroll
                for (int nt = 0; nt < 4; nt++) {
                    int c = wn * 32 + nt * 8 + tid4 * 2;
                    float s0 = silu(sacc[mt][nt][half * 2 + 0] * 0.125f);
                    float s1 = silu(sacc[mt][nt][half * 2 + 1] * 0.125f);
                    if (diag) {
                        if (c > r) s0 = 0.f;
                        if (c + 1 > r) s1 = 0.f;
                    }
                    *(uint32_t*)(sp + r * 136 + c) = pack2h(__float2half(s0), __float2half(s1));
                }
            }
        }
        if (more) CPWAIT(1); else CPWAIT(0);
        __syncthreads();

        #pragma unroll
        for (int ks = 0; ks < 8; ks++) {
            uint32_t s4[4][4], v4[4];
            #pragma unroll
            for (int mt = 0; mt < 4; mt++)
                ldsm4(s4[mt], sb + oS + aOffS + (uint32_t)(mt * 16 * SROWB + ks * 32));
            ldsm4t(v4, sb + oV + bOffV + (uint32_t)(ks * 16 * AROWB));
            #pragma unroll
            for (int mt = 0; mt < 4; mt++)
                #pragma unroll
                for (int nt = 0; nt < 2; nt++) {
                    int o = nt * 2;
                    mma16816(oacc[mt][nt], s4[mt], v4[o], v4[o + 1]);
                }
        }
    }

    __syncthreads();
    #pragma unroll
    for (int mt = 0; mt < 4; mt++)
        #pragma unroll
        for (int half = 0; half < 2; half++) {
            int r = wm * 64 + mt * 16 + groupID + half * 8;
            #pragma unroll
            for (int nt = 0; nt < 2; nt++) {
                int c = wn * 16 + nt * 8 + tid4 * 2;
                float2 v;
                v.x = oacc[mt][nt][half * 2 + 0];
                v.y = oacc[mt][nt][half * 2 + 1];
                *(float2*)(aS + r * 68 + c) = v;
            }
        }
    __syncthreads();
    if (tid < 128) {
        float s = 0.f, s2 = 0.f;
        #pragma unroll
        for (int c = 0; c < 64; c++) {
            float v = aS[tid * 68 + c];
            s += v; s2 += v * v;
        }
        float mu = s * (1.0f / 64.0f);
        float var = s2 * (1.0f / 64.0f) - mu * mu;
        mu_s[tid] = mu;
        rs_s[tid] = rsqrtf(var + 1e-5f);
    }
    __syncthreads();
    {
        int r = tid >> 1;
        int c0 = (tid & 1) * 32;
        int l = qb * 128 + r;
        float mu = mu_s[r], rstd = rs_s[r];
        const __half* uh = (const __half*)(gq + 6144 + (size_t)l * GROWB);
        size_t obase = (size_t)(b * LL + l) * DD + h * HD;
        #pragma unroll
        for (int c = c0; c < c0 + 32; c += 2) {
            float u0 = __half2float(uh[c + 0]);
            float u1 = __half2float(uh[c + 1]);
            float t0 = ((aS[r * 68 + c + 0] - mu) * rstd * nag[c + 0] + nab[c + 0]) * u0;
            float t1 = ((aS[r * 68 + c + 1] - mu) * rstd * nag[c + 1] + nab[c + 1]) * u1;
            *(uint32_t*)(aout + obase + c) = pack2h(__float2half(t0), __float2half(t1));
        }
    }
}

// ---------------- host -------------------------------------------------------
extern "C" void kernel_launch(void* const* d_in, const int* in_sizes, int n_in,
                              void* d_out, int out_size)
{
    const float* x      = (const float*)d_in[0];
    const float* w_qkuv = (const float*)d_in[2];
    const float* w_out  = (const float*)d_in[3];
    const float* w1     = (const float*)d_in[4];
    const float* w2     = (const float*)d_in[5];
    const float* w3     = (const float*)d_in[6];
    const float* ln1_g  = (const float*)d_in[7];
    const float* ln1_b  = (const float*)d_in[8];
    const float* ln2_g  = (const float*)d_in[9];
    const float* ln2_b  = (const float*)d_in[10];
    const float* na_g   = (const float*)d_in[11];
    const float* na_b   = (const float*)d_in[12];
    float* out = (float*)d_out;

    __half *xn, *qk, *a, *xn2, *hbuf;
    __half *wq, *wo, *w1t, *w3t, *w2t;
    float *x1;
    cudaGetSymbolAddress((void**)&xn,   g_xn);
    cudaGetSymbolAddress((void**)&qk,   g_qk);
    cudaGetSymbolAddress((void**)&a,    g_a);
    cudaGetSymbolAddress((void**)&x1,   g_x1);
    cudaGetSymbolAddress((void**)&xn2,  g_xn2);
    cudaGetSymbolAddress((void**)&hbuf, g_h);
    cudaGetSymbolAddress((void**)&wq,   g_wqkuv);
    cudaGetSymbolAddress((void**)&wo,   g_wout);
    cudaGetSymbolAddress((void**)&w1t,  g_w1);
    cudaGetSymbolAddress((void**)&w3t,  g_w3);
    cudaGetSymbolAddress((void**)&w2t,  g_w2);

    cudaFuncSetAttribute(gemm_mma<1>, cudaFuncAttributeMaxDynamicSharedMemorySize, GEMM_SMEM);
    cudaFuncSetAttribute(gemm_mma<3>, cudaFuncAttributeMaxDynamicSharedMemorySize, GEMM_SMEM);
    cudaFuncSetAttribute(gemm_dual,   cudaFuncAttributeMaxDynamicSharedMemorySize, DUAL_SMEM);
    cudaFuncSetAttribute(attn_mma,    cudaFuncAttributeMaxDynamicSharedMemorySize, ATT_SMEM);

    dim3 blk(256);

    // 1. LN1 -> fp16  +  wqkuv convert (fused launch)
    ln_conv_kernel<<<MROWS / 8 + 128, blk>>>(x, ln1_g, ln1_b, xn, w_qkuv, wq);
    // 2. qkuv = silu(xn @ w_qkuv) -> fp16
    gemm_mma<3><<<dim3(4 * DD / 128, MROWS / 128), blk, GEMM_SMEM>>>(
        xn, wq, nullptr, nullptr, qk, MROWS, 4 * DD, DD);
    // 3. attention -> a fp16  +  late weight conversions (fused launch)
    attn_mma<<<ATT_CTAS + CONV_CTAS, blk, ATT_SMEM>>>(
        qk, na_g, na_b, a,
        w_out, wo, w1, w1t, w3, w3t, w2, w2t);
    // 4. x1 = x + a @ w_out
    gemm_mma<1><<<dim3(DD / 128, MROWS / 128), blk, GEMM_SMEM>>>(
        a, wo, x1, x, nullptr, MROWS, DD, DD);
    // 5. LN2 -> fp16
    ln_half_kernel<<<MROWS / 8, blk>>>(x1, ln2_g, ln2_b, xn2);
    // 6+7. h = silu(xn2@w1) * (xn2@w3) -> fp16 (3-stage)
    gemm_dual<<<dim3(FF / 64, MROWS / 128), blk, DUAL_SMEM>>>(
        xn2, w1t, w3t, hbuf, MROWS, FF, DD);
    // 8. out = x1 + h @ w2
    gemm_mma<1><<<dim3(DD / 128, MROWS / 128), blk, GEMM_SMEM>>>(
        hbuf, w2t, out, x1, nullptr, MROWS, DD, FF);
}

// round 17
// speedup vs baseline: 1.0238x; 1.0238x over previous
#include <cuda_runtime.h>
#include <cuda_fp16.h>
#include <cstdint>
#include <math.h>

#define BB 2
#define LL 2048
#define DD 1024
#define HH 16
#define HD 64
#define FF 4096
#define MROWS (BB*LL)   // 4096

// ---------------- scratch (device globals) ---------------------------------
__device__ __half g_xn  [MROWS * DD];
__device__ __half g_qk  [MROWS * 4 * DD];   // silu(xn@w_qkuv) fp16
__device__ __half g_a   [MROWS * DD];
__device__ float  g_x1  [MROWS * DD];
__device__ __half g_xn2 [MROWS * DD];
__device__ __half g_h   [MROWS * FF];
// weights in NATIVE [K, N] layout, fp16 (no transpose)
__device__ __half g_wqkuv [DD * 4 * DD];
__device__ __half g_wout  [DD * DD];
__device__ __half g_w1    [DD * FF];
__device__ __half g_w3    [DD * FF];
__device__ __half g_w2    [FF * DD];

__device__ __forceinline__ float silu(float x) {
    return __fdividef(x, 1.0f + __expf(-x));
}
__device__ __forceinline__ uint32_t smem_u32(const void* p) {
    uint32_t a;
    asm("{ .reg .u64 t; cvta.to.shared.u64 t, %1; cvt.u32.u64 %0, t; }" : "=r"(a) : "l"(p));
    return a;
}
__device__ __forceinline__ void cp16(uint32_t s, const void* g) {
    asm volatile("cp.async.cg.shared.global [%0], [%1], 16;" :: "r"(s), "l"(g) : "memory");
}
#define CPCOMMIT() asm volatile("cp.async.commit_group;" ::: "memory")
#define CPWAIT(n)  asm volatile("cp.async.wait_group %0;" :: "n"(n) : "memory")
__device__ __forceinline__ uint32_t pack2h(__half a, __half b) {
    return (uint32_t)__half_as_ushort(a) | ((uint32_t)__half_as_ushort(b) << 16);
}
__device__ __forceinline__ void ldsm4(uint32_t* r, uint32_t a) {
    asm volatile("ldmatrix.sync.aligned.m8n8.x4.shared.b16 {%0,%1,%2,%3}, [%4];"
        : "=r"(r[0]), "=r"(r[1]), "=r"(r[2]), "=r"(r[3]) : "r"(a));
}
__device__ __forceinline__ void ldsm4t(uint32_t* r, uint32_t a) {
    asm volatile("ldmatrix.sync.aligned.m8n8.x4.trans.shared.b16 {%0,%1,%2,%3}, [%4];"
        : "=r"(r[0]), "=r"(r[1]), "=r"(r[2]), "=r"(r[3]) : "r"(a));
}
__device__ __forceinline__ void mma16816(float* c, const uint32_t* a, uint32_t b0, uint32_t b1) {
    asm volatile(
        "mma.sync.aligned.m16n8k16.row.col.f32.f16.f16.f32 "
        "{%0,%1,%2,%3}, {%4,%5,%6,%7}, {%8,%9}, {%0,%1,%2,%3};"
        : "+f"(c[0]), "+f"(c[1]), "+f"(c[2]), "+f"(c[3])
        : "r"(a[0]), "r"(a[1]), "r"(a[2]), "r"(a[3]), "r"(b0), "r"(b1));
}

// ---------------- fp32 -> fp16 chunk convert (32768 elems per CTA) ----------
__device__ __forceinline__ void conv_chunk(const float* __restrict__ src,
                                           __half* __restrict__ dst,
                                           int cta, int tid)
{
    size_t base = (size_t)cta * 32768;
    #pragma unroll
    for (int it = 0; it < 32; it++) {
        size_t idx = base + (size_t)(it * 256 + tid) * 4;
        float4 v = *(const float4*)(src + idx);
        *(uint2*)(dst + idx) = make_uint2(
            pack2h(__float2half(v.x), __float2half(v.y)),
            pack2h(__float2half(v.z), __float2half(v.w)));
    }
}

// ---------------- LayerNorm row (warp-per-row body) --------------------------
__device__ __forceinline__ void ln_row(const float* __restrict__ xr,
                                       const float* __restrict__ g,
                                       const float* __restrict__ b,
                                       __half* __restrict__ orow, int lid)
{
    float s = 0.f, s2 = 0.f;
    float4 q4[8];
    #pragma unroll
    for (int j = 0; j < 8; j++) {
        q4[j] = *(const float4*)(xr + j * 128 + lid * 4);
        s  += q4[j].x + q4[j].y + q4[j].z + q4[j].w;
        s2 += q4[j].x * q4[j].x + q4[j].y * q4[j].y
            + q4[j].z * q4[j].z + q4[j].w * q4[j].w;
    }
    #pragma unroll
    for (int off = 16; off > 0; off >>= 1) {
        s  += __shfl_xor_sync(0xffffffffu, s,  off);
        s2 += __shfl_xor_sync(0xffffffffu, s2, off);
    }
    float mu = s * (1.0f / DD);
    float var = s2 * (1.0f / DD) - mu * mu;
    float rstd = rsqrtf(var + 1e-5f);
    #pragma unroll
    for (int j = 0; j < 8; j++) {
        int c = j * 128 + lid * 4;
        float4 gg = *(const float4*)(g + c);
        float4 bb = *(const float4*)(b + c);
        __half h0 = __float2half((q4[j].x - mu) * rstd * gg.x + bb.x);
        __half h1 = __float2half((q4[j].y - mu) * rstd * gg.y + bb.y);
        __half h2 = __float2half((q4[j].z - mu) * rstd * gg.z + bb.z);
        __half h3 = __float2half((q4[j].w - mu) * rstd * gg.w + bb.w);
        *(uint2*)(orow + c) = make_uint2(pack2h(h0, h1), pack2h(h2, h3));
    }
}

// ---------------- LN1 + wqkuv convert, fused launch --------------------------
__global__ __launch_bounds__(256) void ln_conv_kernel(
    const float* __restrict__ x, const float* __restrict__ g,
    const float* __restrict__ b, __half* __restrict__ o,
    const float* __restrict__ wsrc, __half* __restrict__ wdst)
{
    int bid = blockIdx.x;
    int wid = threadIdx.x >> 5, lid = threadIdx.x & 31;
    if (bid < MROWS / 8) {
        int row = bid * 8 + wid;
        ln_row(x + (size_t)row * DD, g, b, o + (size_t)row * DD, lid);
    } else {
        conv_chunk(wsrc, wdst, bid - MROWS / 8, threadIdx.x);
    }
}

// ---------------- LayerNorm standalone (LN2) ---------------------------------
__global__ __launch_bounds__(256) void ln_half_kernel(
    const float* __restrict__ x, const float* __restrict__ g,
    const float* __restrict__ b, __half* __restrict__ o)
{
    int wid = threadIdx.x >> 5, lid = threadIdx.x & 31;
    int row = blockIdx.x * 8 + wid;
    ln_row(x + (size_t)row * DD, g, b, o + (size_t)row * DD, lid);
}

// ---------------- fp16 GEMM: D[M,N] = A[M,K] @ W[K,N] ------------------------
// MODE 1: Cf = acc + aux (fp32 out).  MODE 3: silu(acc) -> Ch fp16.
// CTA 128x128, BK=64, warp 64x32 (2x4), 3-stage, 2 CTAs/SM.
// B-fragments double-buffered across ks-slices.
#define SROW 144
#define WROWB 272
#define AT (128 * SROW)             // 18432
#define WT (64 * WROWB)             // 17408
#define STAGE3 (AT + WT)            // 35840
#define GEMM_SMEM (3 * STAGE3)      // 107520

template <int MODE>
__global__ __launch_bounds__(256, 2) void gemm_mma(
    const __half* __restrict__ A, const __half* __restrict__ Bw,
    float* __restrict__ Cf, const float* __restrict__ aux,
    __half* __restrict__ Ch,
    int M, int N, int K)
{
    extern __shared__ char smem[];
    const uint32_t sbase = smem_u32(smem);
    const int tid = threadIdx.x, lane = tid & 31, wid = tid >> 5;
    const int wm = wid & 1, wn = wid >> 1;
    const int bx = blockIdx.x, by = blockIdx.y;

    const size_t rowbytesA = (size_t)K * 2;
    const size_t rowbytesB = (size_t)N * 2;
    const char* Ab = (const char*)(A + (size_t)by * 128 * K);
    const char* Bb = (const char*)Bw + (size_t)bx * 256;

    const uint32_t aRowOff = (uint32_t)((wm * 64 + (lane & 15)) * SROW + (lane >> 4) * 16);
    const int bg = lane >> 3;
    const uint32_t bOffW = (uint32_t)(((bg & 1) * 8 + (lane & 7)) * WROWB
                                      + (wn * 32 + (bg >> 1) * 8) * 2);

    auto load_slab = [&](int ks, int st) {
        uint32_t stg = sbase + (uint32_t)st * STAGE3;
        size_t akoff = (size_t)ks * 128;
        size_t bk0 = (size_t)ks * 64;
        #pragma unroll
        for (int i = 0; i < 8; i++) {
            int c = tid + i * 256;
            if (c < 1024) {
                int rr = c >> 3, ck = (c & 7) * 16;
                cp16(stg + (uint32_t)(rr * SROW + ck),
                     Ab + (size_t)rr * rowbytesA + akoff + ck);
            } else {
                int j = c - 1024;
                int rr = j >> 4, ck = (j & 15) * 16;
                cp16(stg + (uint32_t)(AT + rr * WROWB + ck),
                     Bb + (bk0 + rr) * rowbytesB + ck);
            }
        }
        CPCOMMIT();
    };

    float acc[4][4][4];
    #pragma unroll
    for (int mt = 0; mt < 4; mt++)
        #pragma unroll
        for (int nt = 0; nt < 4; nt++)
            #pragma unroll
            for (int j = 0; j < 4; j++) acc[mt][nt][j] = 0.f;

    const int ns = K >> 6;
    load_slab(0, 0);
    if (ns > 1) load_slab(1, 1);

    for (int i = 0; i < ns; i++) {
        if (i + 1 < ns) CPWAIT(1);
        else            CPWAIT(0);
        __syncthreads();
        if (i + 2 < ns) load_slab(i + 2, (i + 2) % 3);

        uint32_t stg = sbase + (uint32_t)(i % 3) * STAGE3;
        uint32_t aB = stg + aRowOff;
        uint32_t bB = stg + AT + bOffW;

        // B fragments double-buffered across the 4 ks-slices
        uint32_t bh[2][2][4];
        #pragma unroll
        for (int p = 0; p < 2; p++)
            ldsm4t(bh[0][p], bB + (uint32_t)(p * 32));

        #pragma unroll
        for (int ks = 0; ks < 4; ks++) {
            const int cur = ks & 1;
            // prefetch next slice's B fragments before this slice's MMAs
            if (ks < 3) {
                #pragma unroll
                for (int p = 0; p < 2; p++)
                    ldsm4t(bh[cur ^ 1][p], bB + (uint32_t)((ks + 1) * 16 * WROWB + p * 32));
            }
            uint32_t ah[4][4];
            #pragma unroll
            for (int mt = 0; mt < 4; mt++)
                ldsm4(ah[mt], aB + (uint32_t)(mt * 16 * SROW + ks * 32));
            #pragma unroll
            for (int mt = 0; mt < 4; mt++)
                #pragma unroll
                for (int nt = 0; nt < 4; nt++) {
                    int p = nt >> 1, o = (nt & 1) * 2;
                    mma16816(acc[mt][nt], ah[mt], bh[cur][p][o], bh[cur][p][o + 1]);
                }
        }
    }

    const int groupID = lane >> 2, tid4 = lane & 3;
    #pragma unroll
    for (int mt = 0; mt < 4; mt++) {
        int r0 = by * 128 + wm * 64 + mt * 16 + groupID;
        #pragma unroll
        for (int nt = 0; nt < 4; nt++) {
            int cg = bx * 128 + wn * 32 + nt * 8 + tid4 * 2;
            float* a = acc[mt][nt];
            #pragma unroll
            for (int half = 0; half < 2; half++) {
                size_t off = (size_t)(r0 + half * 8) * N + cg;
                float v0 = a[half * 2 + 0], v1 = a[half * 2 + 1];
                if (MODE == 1) {
                    float2 ax = *(const float2*)(aux + off);
                    float2 o; o.x = v0 + ax.x; o.y = v1 + ax.y;
                    *(float2*)(Cf + off) = o;
                } else {
                    *(uint32_t*)(Ch + off) = pack2h(__float2half(silu(v0)),
                                                    __float2half(silu(v1)));
                }
            }
        }
    }
}

// ---------------- dual GEMM: h = silu(A@W1) * (A@W3) -> fp16 (R13 2-stage) ---
#define DWROWB 144
#define DWT (64 * DWROWB)                 // 9216
#define DSTAGE (AT + 2 * DWT)             // 36864
#define DUAL_SMEM (2 * DSTAGE)            // 73728

__global__ __launch_bounds__(256, 2) void gemm_dual(
    const __half* __restrict__ A,
    const __half* __restrict__ B1, const __half* __restrict__ B3,
    __half* __restrict__ Ch,
    int M, int N, int K)
{
    extern __shared__ char smem[];
    const uint32_t sbase = smem_u32(smem);
    const int tid = threadIdx.x, lane = tid & 31, wid = tid >> 5;
    const int wm = wid & 1, wn = wid >> 1;
    const int bx = blockIdx.x, by = blockIdx.y;

    const size_t rowbytesA = (size_t)K * 2;
    const size_t rowbytesB = (size_t)N * 2;
    const char* Ab  = (const char*)(A + (size_t)by * 128 * K);
    const char* B1b = (const char*)B1 + (size_t)bx * 128;
    const char* B3b = (const char*)B3 + (size_t)bx * 128;

    const uint32_t aRowOff = (uint32_t)((wm * 64 + (lane & 15)) * SROW + (lane >> 4) * 16);
    const int bg = lane >> 3;
    const uint32_t bOffW = (uint32_t)(((bg & 1) * 8 + (lane & 7)) * DWROWB
                                      + (wn * 16 + (bg >> 1) * 8) * 2);

    auto load_slab = [&](int ks, int st) {
        uint32_t stg = sbase + (uint32_t)st * DSTAGE;
        size_t akoff = (size_t)ks * 128;
        size_t bk0 = (size_t)ks * 64;
        #pragma unroll
        for (int i = 0; i < 8; i++) {
            int c = tid + i * 256;
            if (c < 1024) {
                int rr = c >> 3, ck = (c & 7) * 16;
                cp16(stg + (uint32_t)(rr * SROW + ck),
                     Ab + (size_t)rr * rowbytesA + akoff + ck);
            } else {
                int j = c - 1024;
                int tw = j >> 9;
                int jj = j & 511;
                int rr = jj >> 3, ck = (jj & 7) * 16;
                cp16(stg + (uint32_t)(AT + tw * DWT + rr * DWROWB + ck),
                     (tw ? B3b : B1b) + (bk0 + rr) * rowbytesB + ck);
            }
        }
        CPCOMMIT();
    };

    float acc1[4][2][4], acc3[4][2][4];
    #pragma unroll
    for (int mt = 0; mt < 4; mt++)
        #pragma unroll
        for (int nt = 0; nt < 2; nt++)
            #pragma unroll
            for (int j = 0; j < 4; j++) { acc1[mt][nt][j] = 0.f; acc3[mt][nt][j] = 0.f; }

    const int ns = K >> 6;
    load_slab(0, 0);

    for (int i = 0; i < ns; i++) {
        CPWAIT(0);
        __syncthreads();
        if (i + 1 < ns) load_slab(i + 1, (i + 1) & 1);

        uint32_t stg = sbase + (uint32_t)(i & 1) * DSTAGE;
        uint32_t aB  = stg + aRowOff;
        uint32_t b1B = stg + AT + bOffW;
        uint32_t b3B = stg + AT + DWT + bOffW;

        #pragma unroll
        for (int ks = 0; ks < 4; ks++) {
            uint32_t ah[4][4], b1h[4], b3h[4];
            #pragma unroll
            for (int mt = 0; mt < 4; mt++)
                ldsm4(ah[mt], aB + (uint32_t)(mt * 16 * SROW + ks * 32));
            uint32_t ko = (uint32_t)(ks * 16 * DWROWB);
            ldsm4t(b1h, b1B + ko);
            ldsm4t(b3h, b3B + ko);
            #pragma unroll
            for (int mt = 0; mt < 4; mt++)
                #pragma unroll
                for (int nt = 0; nt < 2; nt++) {
                    int o = nt * 2;
                    mma16816(acc1[mt][nt], ah[mt], b1h[o], b1h[o + 1]);
                    mma16816(acc3[mt][nt], ah[mt], b3h[o], b3h[o + 1]);
                }
        }
    }

    const int groupID = lane >> 2, tid4 = lane & 3;
    #pragma unroll
    for (int mt = 0; mt < 4; mt++) {
        int r0 = by * 128 + wm * 64 + mt * 16 + groupID;
        #pragma unroll
        for (int nt = 0; nt < 2; nt++) {
            int cg = bx * 64 + wn * 16 + nt * 8 + tid4 * 2;
            #pragma unroll
            for (int half = 0; half < 2; half++) {
                size_t off = (size_t)(r0 + half * 8) * N + cg;
                float t0 = silu(acc1[mt][nt][half * 2 + 0]) * acc3[mt][nt][half * 2 + 0];
                float t1 = silu(acc1[mt][nt][half * 2 + 1]) * acc3[mt][nt][half * 2 + 1];
                *(uint32_t*)(Ch + off) = pack2h(__float2half(t0), __float2half(t1));
            }
        }
    }
}

// ---------------- Fused attention + late weight conversions ------------------
#define AROWB 144
#define SROWB 272
#define ATT_SMEM 108544
#define GROWB 8192
#define ATT_CTAS 512
#define CONV_CTAS 416

__global__ __launch_bounds__(256, 2) void attn_mma(
    const __half* __restrict__ qk,
    const float* __restrict__ nag, const float* __restrict__ nab,
    __half* __restrict__ aout,
    const float* __restrict__ woF, __half* __restrict__ woH,
    const float* __restrict__ w1F, __half* __restrict__ w1H,
    const float* __restrict__ w3F, __half* __restrict__ w3H,
    const float* __restrict__ w2F, __half* __restrict__ w2H)
{
    const int bid = blockIdx.x;
    const int tid = threadIdx.x;
    if (bid >= ATT_CTAS) {
        int j = bid - ATT_CTAS;
        if (j < 32)        conv_chunk(woF, woH, j, tid);
        else if (j < 160)  conv_chunk(w1F, w1H, j - 32, tid);
        else if (j < 288)  conv_chunk(w3F, w3H, j - 160, tid);
        else               conv_chunk(w2F, w2H, j - 288, tid);
        return;
    }

    extern __shared__ char smc[];
    const uint32_t sb = smem_u32(smc);
    const uint32_t oQ = 0;
    const uint32_t oK[2] = {18432, 36864};
    const uint32_t oV = 55296;
    const uint32_t oS = 73728;
    __half* sp = (__half*)(smc + oS);
    float* aS = (float*)(smc + oS);
    __shared__ float mu_s[128], rs_s[128];

    const int qb = 15 - (bid >> 5);
    const int bh = bid & 31;
    const int b = bh >> 4, h = bh & 15;
    const int lane = tid & 31, wid = tid >> 5;
    const int wm = wid & 1, wn = wid >> 1;
    const int groupID = lane >> 2, tid4 = lane & 3;

    const char* gq = (const char*)qk + (size_t)(b * LL) * GROWB + h * 128;

    auto ldt = [&](uint32_t so, const char* g) {
        #pragma unroll
        for (int i = 0; i < 4; i++) {
            int idx = tid + i * 256;
            int r = idx >> 3, ck = (idx & 7) * 16;
            cp16(sb + so + (uint32_t)(r * AROWB + ck), g + (size_t)r * GROWB + ck);
        }
    };

    ldt(oQ, gq + (size_t)(qb * 128) * GROWB);
    ldt(oK[0], gq + 2048);
    CPCOMMIT();

    const uint32_t aOffQ = (uint32_t)((wm * 64 + (lane & 15)) * AROWB + (lane >> 4) * 16);
    const int bg = lane >> 3;
    const uint32_t bOffK = (uint32_t)((wn * 32 + (bg >> 1) * 8 + (lane & 7)) * AROWB + (bg & 1) * 16);
    const uint32_t aOffS = (uint32_t)((wm * 64 + (lane & 15)) * SROWB + (lane >> 4) * 16);
    const uint32_t bOffV = (uint32_t)(((bg & 1) * 8 + (lane & 7)) * AROWB + (wn * 16 + (bg >> 1) * 8) * 2);

    float oacc[4][2][4];
    #pragma unroll
    for (int mt = 0; mt < 4; mt++)
        #pragma unroll
        for (int nt = 0; nt < 2; nt++)
            #pragma unroll
            for (int j = 0; j < 4; j++) oacc[mt][nt][j] = 0.f;

    for (int kb = 0; kb <= qb; kb++) {
        const int st = kb & 1;
        const bool more = (kb < qb);
        __syncthreads();
        ldt(oV, gq + 4096 + (size_t)(kb * 128) * GROWB);
        CPCOMMIT();
        if (more) {
            ldt(oK[st ^ 1], gq + 2048 + (size_t)((kb + 1) * 128) * GROWB);
            CPCOMMIT();
        }
        if (more) CPWAIT(2); else CPWAIT(1);
        __syncthreads();

        float sacc[4][4][4];
        #pragma unroll
        for (int mt = 0; mt < 4; mt++)
            #pragma unroll
            for (int nt = 0; nt < 4; nt++)
                #pragma unroll
                for (int j = 0; j < 4; j++) sacc[mt][nt][j] = 0.f;

        #pragma unroll
        for (int ks = 0; ks < 4; ks++) {
            uint32_t q4[4][4], k4[2][4];
            #pragma unroll
            for (int mt = 0; mt < 4; mt++)
                ldsm4(q4[mt], sb + oQ + aOffQ + (uint32_t)(mt * 16 * AROWB + ks * 32));
            #pragma unroll
            for (int p = 0; p < 2; p++)
                ldsm4(k4[p], sb + oK[st] + bOffK + (uint32_t)(p * 16 * AROWB + ks * 32));
            #pragma unroll
            for (int mt = 0; mt < 4; mt++)
                #pragma unroll
                for (int nt = 0; nt < 4; nt++) {
                    int p = nt >> 1, o = (nt & 1) * 2;
                    mma16816(sacc[mt][nt], q4[mt], k4[p][o], k4[p][o + 1]);
                }
        }

        const bool diag = (kb == qb);
        #pragma unroll
        for (int mt = 0; mt < 4; mt++) {
            #pragma unroll
            for (int half = 0; half < 2; half++) {
                int r = wm * 64 + mt * 16 + groupID + half * 8;
                #pragma unroll
                for (int nt = 0; nt < 4; nt++) {
                    int c = wn * 32 + nt * 8 + tid4 * 2;
                    float s0 = silu(sacc[mt][nt][half * 2 + 0] * 0.125f);
                    float s1 = silu(sacc[mt][nt][half * 2 + 1] * 0.125f);
                    if (diag) {
                        if (c > r) s0 = 0.f;
                        if (c + 1 > r) s1 = 0.f;
                    }
                    *(uint32_t*)(sp + r * 136 + c) = pack2h(__float2half(s0), __float2half(s1));
                }
            }
        }
        if (more) CPWAIT(1); else CPWAIT(0);
        __syncthreads();

        #pragma unroll
        for (int ks = 0; ks < 8; ks++) {
            uint32_t s4[4][4], v4[4];
            #pragma unroll
            for (int mt = 0; mt < 4; mt++)
                ldsm4(s4[mt], sb + oS + aOffS + (uint32_t)(mt * 16 * SROWB + ks * 32));
            ldsm4t(v4, sb + oV + bOffV + (uint32_t)(ks * 16 * AROWB));
            #pragma unroll
            for (int mt = 0; mt < 4; mt++)
                #pragma unroll
                for (int nt = 0; nt < 2; nt++) {
                    int o = nt * 2;
                    mma16816(oacc[mt][nt], s4[mt], v4[o], v4[o + 1]);
                }
        }
    }

    __syncthreads();
    #pragma unroll
    for (int mt = 0; mt < 4; mt++)
        #pragma unroll
        for (int half = 0; half < 2; half++) {
            int r = wm * 64 + mt * 16 + groupID + half * 8;
            #pragma unroll
            for (int nt = 0; nt < 2; nt++) {
                int c = wn * 16 + nt * 8 + tid4 * 2;
                float2 v;
                v.x = oacc[mt][nt][half * 2 + 0];
                v.y = oacc[mt][nt][half * 2 + 1];
                *(float2*)(aS + r * 68 + c) = v;
            }
        }
    __syncthreads();
    if (tid < 128) {
        float s = 0.f, s2 = 0.f;
        #pragma unroll
        for (int c = 0; c < 64; c++) {
            float v = aS[tid * 68 + c];
            s += v; s2 += v * v;
        }
        float mu = s * (1.0f / 64.0f);
        float var = s2 * (1.0f / 64.0f) - mu * mu;
        mu_s[tid] = mu;
        rs_s[tid] = rsqrtf(var + 1e-5f);
    }
    __syncthreads();
    {
        int r = tid >> 1;
        int c0 = (tid & 1) * 32;
        int l = qb * 128 + r;
        float mu = mu_s[r], rstd = rs_s[r];
        const __half* uh = (const __half*)(gq + 6144 + (size_t)l * GROWB);
        size_t obase = (size_t)(b * LL + l) * DD + h * HD;
        #pragma unroll
        for (int c = c0; c < c0 + 32; c += 2) {
            float u0 = __half2float(uh[c + 0]);
            float u1 = __half2float(uh[c + 1]);
            float t0 = ((aS[r * 68 + c + 0] - mu) * rstd * nag[c + 0] + nab[c + 0]) * u0;
            float t1 = ((aS[r * 68 + c + 1] - mu) * rstd * nag[c + 1] + nab[c + 1]) * u1;
            *(uint32_t*)(aout + obase + c) = pack2h(__float2half(t0), __float2half(t1));
        }
    }
}

// ---------------- host -------------------------------------------------------
extern "C" void kernel_launch(void* const* d_in, const int* in_sizes, int n_in,
                              void* d_out, int out_size)
{
    const float* x      = (const float*)d_in[0];
    const float* w_qkuv = (const float*)d_in[2];
    const float* w_out  = (const float*)d_in[3];
    const float* w1     = (const float*)d_in[4];
    const float* w2     = (const float*)d_in[5];
    const float* w3     = (const float*)d_in[6];
    const float* ln1_g  = (const float*)d_in[7];
    const float* ln1_b  = (const float*)d_in[8];
    const float* ln2_g  = (const float*)d_in[9];
    const float* ln2_b  = (const float*)d_in[10];
    const float* na_g   = (const float*)d_in[11];
    const float* na_b   = (const float*)d_in[12];
    float* out = (float*)d_out;

    __half *xn, *qk, *a, *xn2, *hbuf;
    __half *wq, *wo, *w1t, *w3t, *w2t;
    float *x1;
    cudaGetSymbolAddress((void**)&xn,   g_xn);
    cudaGetSymbolAddress((void**)&qk,   g_qk);
    cudaGetSymbolAddress((void**)&a,    g_a);
    cudaGetSymbolAddress((void**)&x1,   g_x1);
    cudaGetSymbolAddress((void**)&xn2,  g_xn2);
    cudaGetSymbolAddress((void**)&hbuf, g_h);
    cudaGetSymbolAddress((void**)&wq,   g_wqkuv);
    cudaGetSymbolAddress((void**)&wo,   g_wout);
    cudaGetSymbolAddress((void**)&w1t,  g_w1);
    cudaGetSymbolAddress((void**)&w3t,  g_w3);
    cudaGetSymbolAddress((void**)&w2t,  g_w2);

    cudaFuncSetAttribute(gemm_mma<1>, cudaFuncAttributeMaxDynamicSharedMemorySize, GEMM_SMEM);
    cudaFuncSetAttribute(gemm_mma<3>, cudaFuncAttributeMaxDynamicSharedMemorySize, GEMM_SMEM);
    cudaFuncSetAttribute(gemm_dual,   cudaFuncAttributeMaxDynamicSharedMemorySize, DUAL_SMEM);
    cudaFuncSetAttribute(attn_mma,    cudaFuncAttributeMaxDynamicSharedMemorySize, ATT_SMEM);

    dim3 blk(256);

    // 1. LN1 -> fp16  +  wqkuv convert (fused launch)
    ln_conv_kernel<<<MROWS / 8 + 128, blk>>>(x, ln1_g, ln1_b, xn, w_qkuv, wq);
    // 2. qkuv = silu(xn @ w_qkuv) -> fp16
    gemm_mma<3><<<dim3(4 * DD / 128, MROWS / 128), blk, GEMM_SMEM>>>(
        xn, wq, nullptr, nullptr, qk, MROWS, 4 * DD, DD);
    // 3. attention -> a fp16  +  late weight conversions (fused launch)
    attn_mma<<<ATT_CTAS + CONV_CTAS, blk, ATT_SMEM>>>(
        qk, na_g, na_b, a,
        w_out, wo, w1, w1t, w3, w3t, w2, w2t);
    // 4. x1 = x + a @ w_out
    gemm_mma<1><<<dim3(DD / 128, MROWS / 128), blk, GEMM_SMEM>>>(
        a, wo, x1, x, nullptr, MROWS, DD, DD);
    // 5. LN2 -> fp16
    ln_half_kernel<<<MROWS / 8, blk>>>(x1, ln2_g, ln2_b, xn2);
    // 6+7. h = silu(xn2@w1) * (xn2@w3) -> fp16
    gemm_dual<<<dim3(FF / 64, MROWS / 128), blk, DUAL_SMEM>>>(
        xn2, w1t, w3t, hbuf, MROWS, FF, DD);
    // 8. out = x1 + h @ w2
    gemm_mma<1><<<dim3(DD / 128, MROWS / 128), blk, GEMM_SMEM>>>(
        hbuf, w2t, out, x1, nullptr, MROWS, DD, FF);
}